// round 2
// baseline (speedup 1.0000x reference)
#include <cuda_runtime.h>

// Problem constants
#define C 8
#define L 4096
#define NN 4096
#define D 128
#define V 100000

#define BM 64
#define BN 64
#define THREADS 256

// smem strides (floats)
#define SH_STRIDE 132   // sH  [64][132]
#define SET_STRIDE 68   // sEt [128][68]
#define SE_STRIDE 132   // sE  [64][132]
#define SPT_STRIDE 68   // sPt [64][68]

// scratch: gathered embeddings [C, N, D] fp32 (16 MB)
__device__ float g_emb[(size_t)C * NN * D];
__device__ int   g_is64;   // 1 if ngram buffer is int64-layout, 0 if int32

// ---------------------------------------------------------------------------
// Kernel 0: detect token dtype layout. int64 little-endian => every odd int32
// word of the first 64 is the (zero) high half. For genuine int32 tokens
// uniform in [0,1e5), P(32 odd words all zero) ~ 1e-160.
// ---------------------------------------------------------------------------
__global__ void detect_kernel(const int* __restrict__ ngram32) {
    int all_odd_zero = 1;
    for (int i = 1; i < 64; i += 2)
        if (ngram32[i] != 0) { all_odd_zero = 0; break; }
    g_is64 = all_odd_zero;
}

// ---------------------------------------------------------------------------
// Kernel 1: gather emb[c,n,:] = W_emb[ngram_seq[c,n], :]   (float4 granularity)
// ---------------------------------------------------------------------------
__global__ void gather_kernel(const int* __restrict__ ngram32,
                              const float* __restrict__ Wemb) {
    int f4 = blockIdx.x * blockDim.x + threadIdx.x;   // 0 .. C*N*32-1
    int d4 = f4 & 31;
    int idx = f4 >> 5;                                // c*NN + n
    // tokens < 2^31, so for int64 layout the low (even) word suffices
    int tok = g_is64 ? ngram32[2 * idx] : ngram32[idx];
    float4 v = ((const float4*)Wemb)[(size_t)tok * 32 + d4];
    ((float4*)g_emb)[f4] = v;
}

// ---------------------------------------------------------------------------
// Kernel 2: fused attention per (l-tile, channel).
// grid = (L/BM, C), block = 256 threads (16x16)
// ---------------------------------------------------------------------------
__global__ __launch_bounds__(THREADS, 1)
void attn_kernel(const float* __restrict__ H,
                 const float* __restrict__ mask,
                 float* __restrict__ out) {
    const int c  = blockIdx.y;
    const int l0 = blockIdx.x * BM;
    const int t  = threadIdx.x;
    const int tx = t & 15;     // 0..15 -> n-cols (GEMM1) / d-cols (GEMM2)
    const int ty = t >> 4;     // 0..15 -> l-rows

    extern __shared__ float sm[];
    float* sH   = sm;                          // 64*132
    float* sEt  = sH  + 64 * SH_STRIDE;        // 128*68  E^T  [k][n]
    float* sE   = sEt + 128 * SET_STRIDE;      // 64*132  E    [n][k]
    float* sPt  = sE  + 64 * SE_STRIDE;        // 64*68   P^T  [n][l]
    float* sSum = sPt + 64 * SPT_STRIDE;       // 64

    // ---- load H tile [64][128] (once) ----
    #pragma unroll
    for (int j = 0; j < 8; j++) {
        int f4  = j * 256 + t;       // 2048 float4
        int row = f4 >> 5;           // 32 float4 per row
        int c4  = f4 & 31;
        float4 v = ((const float4*)H)[(size_t)(l0 + row) * 32 + c4];
        *(float4*)&sH[row * SH_STRIDE + c4 * 4] = v;
    }
    if (t < 64) sSum[t] = 0.0f;

    float o[4][8];
    #pragma unroll
    for (int i = 0; i < 4; i++)
        #pragma unroll
        for (int j = 0; j < 8; j++) o[i][j] = 0.0f;

    const float inv_temper = 0.08838834764831845f;   // 1/sqrt(128)
    const float4* embBase = (const float4*)g_emb + (size_t)c * NN * 32;
    const float* hRow = &sH[(4 * ty) * SH_STRIDE];

    for (int n0 = 0; n0 < NN; n0 += BN) {
        __syncthreads();   // protect sE/sEt/sPt from previous iteration readers

        // ---- load E tile: natural sE[n][k] + transposed sEt[k][n] ----
        #pragma unroll
        for (int j = 0; j < 8; j++) {
            int f4 = j * 256 + t;
            int n  = f4 & 63;
            int kc = f4 >> 6;   // 0..31 (float4 index along k)
            float4 v = embBase[(size_t)(n0 + n) * 32 + kc];
            *(float4*)&sE[n * SE_STRIDE + kc * 4] = v;
            int k0 = kc * 4;
            sEt[(k0 + 0) * SET_STRIDE + n] = v.x;
            sEt[(k0 + 1) * SET_STRIDE + n] = v.y;
            sEt[(k0 + 2) * SET_STRIDE + n] = v.z;
            sEt[(k0 + 3) * SET_STRIDE + n] = v.w;
        }

        // ---- prefetch mask tile to registers (read-once, no smem) ----
        float4 m[4];
        #pragma unroll
        for (int i = 0; i < 4; i++)
            m[i] = *(const float4*)&mask[((size_t)c * L + (l0 + 4 * ty + i)) * NN
                                         + n0 + 4 * tx];
        __syncthreads();

        // ---- GEMM1: S[4][4] = H-tile rows x E-tile rows ----
        float s[4][4];
        #pragma unroll
        for (int i = 0; i < 4; i++)
            #pragma unroll
            for (int j = 0; j < 4; j++) s[i][j] = 0.0f;

        #pragma unroll 4
        for (int k = 0; k < D; k++) {
            float a0 = hRow[0 * SH_STRIDE + k];
            float a1 = hRow[1 * SH_STRIDE + k];
            float a2 = hRow[2 * SH_STRIDE + k];
            float a3 = hRow[3 * SH_STRIDE + k];
            float4 b = *(const float4*)&sEt[k * SET_STRIDE + 4 * tx];
            s[0][0] += a0 * b.x; s[0][1] += a0 * b.y; s[0][2] += a0 * b.z; s[0][3] += a0 * b.w;
            s[1][0] += a1 * b.x; s[1][1] += a1 * b.y; s[1][2] += a1 * b.z; s[1][3] += a1 * b.w;
            s[2][0] += a2 * b.x; s[2][1] += a2 * b.y; s[2][2] += a2 * b.z; s[2][3] += a2 * b.w;
            s[3][0] += a3 * b.x; s[3][1] += a3 * b.y; s[3][2] += a3 * b.z; s[3][3] += a3 * b.w;
        }

        // ---- exp * clip(mask), store P^T ----
        #pragma unroll
        for (int i = 0; i < 4; i++) {
            float mm0 = fminf(fmaxf(m[i].x, 0.0f), 1.0f);
            float mm1 = fminf(fmaxf(m[i].y, 0.0f), 1.0f);
            float mm2 = fminf(fmaxf(m[i].z, 0.0f), 1.0f);
            float mm3 = fminf(fmaxf(m[i].w, 0.0f), 1.0f);
            int r = 4 * ty + i;
            sPt[(4 * tx + 0) * SPT_STRIDE + r] = __expf(s[i][0] * inv_temper) * mm0;
            sPt[(4 * tx + 1) * SPT_STRIDE + r] = __expf(s[i][1] * inv_temper) * mm1;
            sPt[(4 * tx + 2) * SPT_STRIDE + r] = __expf(s[i][2] * inv_temper) * mm2;
            sPt[(4 * tx + 3) * SPT_STRIDE + r] = __expf(s[i][3] * inv_temper) * mm3;
        }
        __syncthreads();

        // ---- row sums (threads 0..63, one l-row each) ----
        if (t < 64) {
            float rs = 0.0f;
            #pragma unroll
            for (int n = 0; n < BN; n++) rs += sPt[n * SPT_STRIDE + t];
            sSum[t] += rs;
        }

        // ---- GEMM2: O[4][8] += P^T columns x E rows ----
        #pragma unroll 2
        for (int n = 0; n < BN; n++) {
            float4 p  = *(const float4*)&sPt[n * SPT_STRIDE + 4 * ty];
            float4 b0 = *(const float4*)&sE[n * SE_STRIDE + 8 * tx];
            float4 b1 = *(const float4*)&sE[n * SE_STRIDE + 8 * tx + 4];
            o[0][0] += p.x * b0.x; o[0][1] += p.x * b0.y; o[0][2] += p.x * b0.z; o[0][3] += p.x * b0.w;
            o[0][4] += p.x * b1.x; o[0][5] += p.x * b1.y; o[0][6] += p.x * b1.z; o[0][7] += p.x * b1.w;
            o[1][0] += p.y * b0.x; o[1][1] += p.y * b0.y; o[1][2] += p.y * b0.z; o[1][3] += p.y * b0.w;
            o[1][4] += p.y * b1.x; o[1][5] += p.y * b1.y; o[1][6] += p.y * b1.z; o[1][7] += p.y * b1.w;
            o[2][0] += p.z * b0.x; o[2][1] += p.z * b0.y; o[2][2] += p.z * b0.z; o[2][3] += p.z * b0.w;
            o[2][4] += p.z * b1.x; o[2][5] += p.z * b1.y; o[2][6] += p.z * b1.z; o[2][7] += p.z * b1.w;
            o[3][0] += p.w * b0.x; o[3][1] += p.w * b0.y; o[3][2] += p.w * b0.z; o[3][3] += p.w * b0.w;
            o[3][4] += p.w * b1.x; o[3][5] += p.w * b1.y; o[3][6] += p.w * b1.z; o[3][7] += p.w * b1.w;
        }
    }
    __syncthreads();

    // ---- normalize + writeout: out[l, c*D + d] ----
    #pragma unroll
    for (int i = 0; i < 4; i++) {
        float inv = 1.0f / (sSum[4 * ty + i] + 1e-10f);
        float4 w0 = make_float4(o[i][0] * inv, o[i][1] * inv, o[i][2] * inv, o[i][3] * inv);
        float4 w1 = make_float4(o[i][4] * inv, o[i][5] * inv, o[i][6] * inv, o[i][7] * inv);
        size_t base = (size_t)(l0 + 4 * ty + i) * (C * D) + c * D + 8 * tx;
        *(float4*)&out[base]     = w0;
        *(float4*)&out[base + 4] = w1;
    }
}

// ---------------------------------------------------------------------------
// Inputs (metadata order):
//  0: ngram_seq              int32 or int64 (self-detected)  [C, N]
//  1: hidden_state           fp32   [L, D]
//  2: word_ngram_mask_matrix fp32   [C, L, N]
//  3: channel_ids            (dead: softmax over size-1 dim == 1)
//  4: W_emb                  fp32   [V, D]
//  5: W_channel              fp32   [C, 1]  (dead)
// output: fp32 [L, C*D]
// ---------------------------------------------------------------------------
extern "C" void kernel_launch(void* const* d_in, const int* in_sizes, int n_in,
                              void* d_out, int out_size) {
    const int*   ngram32 = (const int*)d_in[0];
    const float* H       = (const float*)d_in[1];
    const float* mask    = (const float*)d_in[2];
    const float* Wemb    = (const float*)d_in[4];
    float*       out     = (float*)d_out;

    const size_t smem_bytes = (64 * SH_STRIDE + 128 * SET_STRIDE +
                               64 * SE_STRIDE + 64 * SPT_STRIDE + 64) * sizeof(float);
    cudaFuncSetAttribute(attn_kernel, cudaFuncAttributeMaxDynamicSharedMemorySize,
                         (int)smem_bytes);

    // Kernel 0: detect int32 vs int64 token layout
    detect_kernel<<<1, 1>>>(ngram32);
    // Kernel 1: gather embeddings
    {
        int total_f4 = C * NN * (D / 4);           // 1,048,576
        gather_kernel<<<total_f4 / THREADS, THREADS>>>(ngram32, Wemb);
    }
    // Kernel 2: fused attention
    {
        dim3 grid(L / BM, C);
        attn_kernel<<<grid, THREADS, smem_bytes>>>(H, mask, out);
    }
}

// round 7
// speedup vs baseline: 4.3264x; 4.3264x over previous
#include <cuda_runtime.h>
#include <cuda_bf16.h>
#include <cstdint>

#define C 8
#define L 4096
#define NN 4096
#define D 128
#define V 100000

// ---------------------------------------------------------------------------
// scratch + dtype flag
// ---------------------------------------------------------------------------
__device__ float g_emb[(size_t)C * NN * D];   // gathered embeddings, 16 MB
__device__ int   g_is64;

// ---------------------------------------------------------------------------
// helpers
// ---------------------------------------------------------------------------
__device__ __forceinline__ float tf32r(float x) {
    float y; asm("cvt.rna.tf32.f32 %0, %1;" : "=f"(y) : "f"(x)); return y;
}
__device__ __forceinline__ uint32_t pack_bf2(float x, float y) {
    __nv_bfloat162 h = __floats2bfloat162_rn(x, y);   // .x = x (low 16 bits)
    return *(uint32_t*)&h;
}
__device__ __forceinline__ void mma_bf16(float c[4], const uint32_t a[4],
                                         uint32_t b0, uint32_t b1) {
    asm volatile("mma.sync.aligned.m16n8k16.row.col.f32.bf16.bf16.f32 "
                 "{%0,%1,%2,%3}, {%4,%5,%6,%7}, {%8,%9}, {%0,%1,%2,%3};"
                 : "+f"(c[0]), "+f"(c[1]), "+f"(c[2]), "+f"(c[3])
                 : "r"(a[0]), "r"(a[1]), "r"(a[2]), "r"(a[3]), "r"(b0), "r"(b1));
}
__device__ __forceinline__ void mma_tf32(float c[4], const uint32_t a[4],
                                         uint32_t b0, uint32_t b1) {
    asm volatile("mma.sync.aligned.m16n8k8.row.col.f32.tf32.tf32.f32 "
                 "{%0,%1,%2,%3}, {%4,%5,%6,%7}, {%8,%9}, {%0,%1,%2,%3};"
                 : "+f"(c[0]), "+f"(c[1]), "+f"(c[2]), "+f"(c[3])
                 : "r"(a[0]), "r"(a[1]), "r"(a[2]), "r"(a[3]), "r"(b0), "r"(b1));
}

// ---------------------------------------------------------------------------
// Kernel 0/1: dtype detect + gather (unchanged from passing R2)
// ---------------------------------------------------------------------------
__global__ void detect_kernel(const int* __restrict__ ngram32) {
    int all_odd_zero = 1;
    for (int i = 1; i < 64; i += 2)
        if (ngram32[i] != 0) { all_odd_zero = 0; break; }
    g_is64 = all_odd_zero;
}
__global__ void gather_kernel(const int* __restrict__ ngram32, const float* __restrict__ Wemb) {
    int f4 = blockIdx.x * blockDim.x + threadIdx.x;
    int d4 = f4 & 31;
    int idx = f4 >> 5;
    int tok = g_is64 ? ngram32[2 * idx] : ngram32[idx];
    float4 v = ((const float4*)Wemb)[(size_t)tok * 32 + d4];
    ((float4*)g_emb)[f4] = v;
}

// ---------------------------------------------------------------------------
// smem layout (bytes).
//   bf16 tiles: 68 words/row (64 data + 4 pad). stride mod 32 = 4
//       -> frag load banks (4g + tig) distinct over a warp.
//   E32: 136 floats/row (mod 32 = 8) -> B-frag banks (8*tig + g) distinct.
//   P:   72 floats/row  (mod 32 = 8) -> A-frag banks (8*g + tig) distinct.
// ---------------------------------------------------------------------------
#define HSTR 68
#define ESTR 68
#define E3STR 136
#define PSTR 72
#define OFF_HHI 0u
#define OFF_HLO (OFF_HHI + 128u * HSTR * 4u)     //  34816
#define OFF_EHI (OFF_HLO + 128u * HSTR * 4u)     //  69632
#define OFF_ELO (OFF_EHI + 64u * ESTR * 4u)      //  87040
#define OFF_E32 (OFF_ELO + 64u * ESTR * 4u)      // 104448
#define OFF_P   (OFF_E32 + 64u * E3STR * 4u)     // 139264
#define OFF_RED (OFF_P   + 128u * PSTR * 4u)     // 176128
#define SMEM_TOTAL (OFF_RED + 512u)              // 176640

// ---------------------------------------------------------------------------
// Kernel 2: fused attention. grid=(L/128, C), block=256 (8 warps).
// GEMM1: bf16 3-pass (Ah*Bh + Ah*Bl + Al*Bh), warp tile 32m x 32n.
// GEMM2: tf32 1-pass, warp tile 32l x 64d, O persistent in registers.
// ---------------------------------------------------------------------------
__global__ __launch_bounds__(256, 1)
void attn_kernel(const float* __restrict__ H,
                 const float* __restrict__ mask,
                 float* __restrict__ out) {
    extern __shared__ char sm[];
    uint32_t* Hh = (uint32_t*)(sm + OFF_HHI);   // [128][68] words (2 bf16/word)
    uint32_t* Hl = (uint32_t*)(sm + OFF_HLO);
    uint32_t* Eh = (uint32_t*)(sm + OFF_EHI);   // [64][68]
    uint32_t* El = (uint32_t*)(sm + OFF_ELO);
    float*    E3 = (float*)(sm + OFF_E32);      // [64][136]
    float*    Pm = (float*)(sm + OFF_P);        // [128][72]
    float*    Rd = (float*)(sm + OFF_RED);      // [128]

    const int t = threadIdx.x, lane = t & 31, warp = t >> 5;
    const int g = lane >> 2, tig = lane & 3;
    const int wm = warp >> 1, wn = warp & 1;    // warp roles
    const int c = blockIdx.y, l0 = blockIdx.x * 128;

    // ---- load + split H tile [128 l][128 d] ----
    #pragma unroll
    for (int j = 0; j < 16; j++) {
        int i = t + 256 * j;                    // 4096 float4
        int row = i >> 5, c4 = i & 31;
        float4 v = ((const float4*)H)[(size_t)(l0 + row) * 32 + c4];
        float hx = __bfloat162float(__float2bfloat16(v.x));
        float hy = __bfloat162float(__float2bfloat16(v.y));
        float hz = __bfloat162float(__float2bfloat16(v.z));
        float hw = __bfloat162float(__float2bfloat16(v.w));
        uint32_t* ph = &Hh[row * HSTR + c4 * 2];
        ph[0] = pack_bf2(v.x, v.y); ph[1] = pack_bf2(v.z, v.w);
        uint32_t* pl = &Hl[row * HSTR + c4 * 2];
        pl[0] = pack_bf2(v.x - hx, v.y - hy); pl[1] = pack_bf2(v.z - hz, v.w - hw);
    }
    if (t < 128) Rd[t] = 0.0f;

    float O[2][8][4];
    #pragma unroll
    for (int a = 0; a < 2; a++)
        #pragma unroll
        for (int b = 0; b < 8; b++)
            #pragma unroll
            for (int q = 0; q < 4; q++) O[a][b][q] = 0.0f;
    float rs[2][2] = {{0.f, 0.f}, {0.f, 0.f}};

    const float INV_T = 0.08838834764831845f;   // 1/sqrt(128)
    const float4* embBase = (const float4*)g_emb + (size_t)c * NN * 32;
    const float*  mwarp = mask + ((size_t)c * L + (l0 + wm * 32)) * NN + wn * 32;

    for (int tt = 0; tt < 64; tt++) {
        const int n0 = tt * 64;
        __syncthreads();   // previous tile's GEMM2 done -> E/P smem reusable

        // ---- load + split E tile [64 n][128 d] ----
        #pragma unroll
        for (int j = 0; j < 8; j++) {
            int i = t + 256 * j;                // 2048 float4
            int row = i >> 5, c4 = i & 31;
            float4 v = embBase[(size_t)(n0 + row) * 32 + c4];
            float hx = __bfloat162float(__float2bfloat16(v.x));
            float hy = __bfloat162float(__float2bfloat16(v.y));
            float hz = __bfloat162float(__float2bfloat16(v.z));
            float hw = __bfloat162float(__float2bfloat16(v.w));
            uint32_t* ph = &Eh[row * ESTR + c4 * 2];
            ph[0] = pack_bf2(v.x, v.y); ph[1] = pack_bf2(v.z, v.w);
            uint32_t* pl = &El[row * ESTR + c4 * 2];
            pl[0] = pack_bf2(v.x - hx, v.y - hy); pl[1] = pack_bf2(v.z - hz, v.w - hw);
            float4 r = make_float4(tf32r(v.x), tf32r(v.y), tf32r(v.z), tf32r(v.w));
            *(float4*)&E3[row * E3STR + c4 * 4] = r;
        }
        __syncthreads();

        // ---- mask prefetch into fragment layout (overlaps GEMM1) ----
        float2 mreg[2][2][4];
        {
            const float* mt = mwarp + n0;
            #pragma unroll
            for (int mc = 0; mc < 2; mc++)
                #pragma unroll
                for (int h = 0; h < 2; h++)
                    #pragma unroll
                    for (int nc = 0; nc < 4; nc++)
                        mreg[mc][h][nc] = *(const float2*)&mt[
                            (size_t)(mc * 16 + g + 8 * h) * NN + nc * 8 + 2 * tig];
        }

        // ---- GEMM1: S = 3-pass bf16 ----
        float S[2][4][4];
        #pragma unroll
        for (int a = 0; a < 2; a++)
            #pragma unroll
            for (int b = 0; b < 4; b++)
                #pragma unroll
                for (int q = 0; q < 4; q++) S[a][b][q] = 0.0f;

        #pragma unroll
        for (int kk = 0; kk < 8; kk++) {
            // word within row for k16 chunk kk: kk*8 + tig ; k+8 half: +4 words
            uint32_t ah[2][4], al[2][4];
            #pragma unroll
            for (int mc = 0; mc < 2; mc++) {
                int r = (wm * 32 + mc * 16 + g) * HSTR + kk * 8 + tig;
                ah[mc][0] = Hh[r];              ah[mc][2] = Hh[r + 4];
                ah[mc][1] = Hh[r + 8 * HSTR];   ah[mc][3] = Hh[r + 8 * HSTR + 4];
                al[mc][0] = Hl[r];              al[mc][2] = Hl[r + 4];
                al[mc][1] = Hl[r + 8 * HSTR];   al[mc][3] = Hl[r + 8 * HSTR + 4];
            }
            uint32_t bh[4][2], bl[4][2];
            #pragma unroll
            for (int nc = 0; nc < 4; nc++) {
                int r = (wn * 32 + nc * 8 + g) * ESTR + kk * 8 + tig;
                bh[nc][0] = Eh[r]; bh[nc][1] = Eh[r + 4];
                bl[nc][0] = El[r]; bl[nc][1] = El[r + 4];
            }
            #pragma unroll
            for (int mc = 0; mc < 2; mc++)
                #pragma unroll
                for (int nc = 0; nc < 4; nc++) {
                    mma_bf16(S[mc][nc], ah[mc], bh[nc][0], bh[nc][1]);
                    mma_bf16(S[mc][nc], ah[mc], bl[nc][0], bl[nc][1]);
                    mma_bf16(S[mc][nc], al[mc], bh[nc][0], bh[nc][1]);
                }
        }

        // ---- epilogue: P = exp(S/temper)*clip(mask), store to smem (tf32) ----
        #pragma unroll
        for (int mc = 0; mc < 2; mc++)
            #pragma unroll
            for (int h = 0; h < 2; h++) {
                int row = wm * 32 + mc * 16 + g + 8 * h;
                #pragma unroll
                for (int nc = 0; nc < 4; nc++) {
                    float2 m = mreg[mc][h][nc];
                    float m0 = fminf(fmaxf(m.x, 0.0f), 1.0f);
                    float m1 = fminf(fmaxf(m.y, 0.0f), 1.0f);
                    float p0 = __expf(S[mc][nc][2 * h + 0] * INV_T) * m0;
                    float p1 = __expf(S[mc][nc][2 * h + 1] * INV_T) * m1;
                    rs[mc][h] += p0 + p1;
                    *(float2*)&Pm[row * PSTR + wn * 32 + nc * 8 + 2 * tig] =
                        make_float2(tf32r(p0), tf32r(p1));
                }
            }
        __syncthreads();   // P (and E32) visible to all warps

        // ---- GEMM2: O += P(tf32) x E32, warp tile 32l x 64d ----
        uint32_t* Pw = (uint32_t*)Pm;
        uint32_t* Ew = (uint32_t*)E3;
        #pragma unroll
        for (int kc = 0; kc < 8; kc++) {
            uint32_t pa[2][4];
            #pragma unroll
            for (int mc = 0; mc < 2; mc++) {
                int r = (wm * 32 + mc * 16 + g) * PSTR + kc * 8 + tig;
                pa[mc][0] = Pw[r];              pa[mc][2] = Pw[r + 4];
                pa[mc][1] = Pw[r + 8 * PSTR];   pa[mc][3] = Pw[r + 8 * PSTR + 4];
            }
            #pragma unroll
            for (int nc = 0; nc < 8; nc++) {
                int bw = (kc * 8 + tig) * E3STR + wn * 64 + nc * 8 + g;
                uint32_t b0 = Ew[bw], b1 = Ew[bw + 4 * E3STR];
                mma_tf32(O[0][nc], pa[0], b0, b1);
                mma_tf32(O[1][nc], pa[1], b0, b1);
            }
        }
    }

    // ---- rowsum reduce: quad shfl + smem atomic ----
    #pragma unroll
    for (int mc = 0; mc < 2; mc++)
        #pragma unroll
        for (int h = 0; h < 2; h++) {
            float v = rs[mc][h];
            v += __shfl_xor_sync(0xFFFFFFFFu, v, 1);
            v += __shfl_xor_sync(0xFFFFFFFFu, v, 2);
            if (tig == 0) atomicAdd(&Rd[wm * 32 + mc * 16 + g + 8 * h], v);
        }
    __syncthreads();

    // ---- normalize + writeout ----
    #pragma unroll
    for (int mc = 0; mc < 2; mc++)
        #pragma unroll
        for (int h = 0; h < 2; h++) {
            int row = wm * 32 + mc * 16 + g + 8 * h;
            float inv = 1.0f / (Rd[row] + 1e-10f);
            float* orow = out + (size_t)(l0 + row) * (C * D) + c * D + wn * 64;
            #pragma unroll
            for (int nc = 0; nc < 8; nc++)
                *(float2*)&orow[nc * 8 + 2 * tig] =
                    make_float2(O[mc][nc][2 * h + 0] * inv,
                                O[mc][nc][2 * h + 1] * inv);
        }
}

// ---------------------------------------------------------------------------
extern "C" void kernel_launch(void* const* d_in, const int* in_sizes, int n_in,
                              void* d_out, int out_size) {
    const int*   ngram32 = (const int*)d_in[0];
    const float* H       = (const float*)d_in[1];
    const float* mask    = (const float*)d_in[2];
    const float* Wemb    = (const float*)d_in[4];
    float*       out     = (float*)d_out;

    cudaFuncSetAttribute(attn_kernel, cudaFuncAttributeMaxDynamicSharedMemorySize, SMEM_TOTAL);

    detect_kernel<<<1, 1>>>(ngram32);
    gather_kernel<<<C * NN * (D / 4) / 256, 256>>>(ngram32, Wemb);
    dim3 grid(L / 128, C);
    attn_kernel<<<grid, 256, SMEM_TOTAL>>>(H, mask, out);
}

// round 8
// speedup vs baseline: 5.4072x; 1.2498x over previous
#include <cuda_runtime.h>
#include <cuda_bf16.h>
#include <cstdint>

#define C 8
#define L 4096
#define NN 4096
#define D 128
#define V 100000

// ---------------------------------------------------------------------------
// precomputed embedding forms + dtype flag
// ---------------------------------------------------------------------------
__device__ uint32_t g_ebh[(size_t)C * NN * 64];   // bf16(E) packed pairs, 8 MB
__device__ float    g_e32[(size_t)C * NN * D];    // tf32-rounded E, 16 MB
__device__ int      g_is64;

// ---------------------------------------------------------------------------
// helpers
// ---------------------------------------------------------------------------
__device__ __forceinline__ uint32_t smem_u32(const void* p) {
    uint32_t a;
    asm("{ .reg .u64 t; cvta.to.shared.u64 t, %1; cvt.u32.u64 %0, t; }" : "=r"(a) : "l"(p));
    return a;
}
__device__ __forceinline__ float tf32r(float x) {
    float y; asm("cvt.rna.tf32.f32 %0, %1;" : "=f"(y) : "f"(x)); return y;
}
__device__ __forceinline__ uint32_t pack_bf2(float x, float y) {
    __nv_bfloat162 h = __floats2bfloat162_rn(x, y);
    return *(uint32_t*)&h;
}
__device__ __forceinline__ void mma_bf16(float c[4], const uint32_t a[4],
                                         uint32_t b0, uint32_t b1) {
    asm volatile("mma.sync.aligned.m16n8k16.row.col.f32.bf16.bf16.f32 "
                 "{%0,%1,%2,%3}, {%4,%5,%6,%7}, {%8,%9}, {%0,%1,%2,%3};"
                 : "+f"(c[0]), "+f"(c[1]), "+f"(c[2]), "+f"(c[3])
                 : "r"(a[0]), "r"(a[1]), "r"(a[2]), "r"(a[3]), "r"(b0), "r"(b1));
}
__device__ __forceinline__ void mma_tf32(float c[4], const uint32_t a[4],
                                         uint32_t b0, uint32_t b1) {
    asm volatile("mma.sync.aligned.m16n8k8.row.col.f32.tf32.tf32.f32 "
                 "{%0,%1,%2,%3}, {%4,%5,%6,%7}, {%8,%9}, {%0,%1,%2,%3};"
                 : "+f"(c[0]), "+f"(c[1]), "+f"(c[2]), "+f"(c[3])
                 : "r"(a[0]), "r"(a[1]), "r"(a[2]), "r"(a[3]), "r"(b0), "r"(b1));
}
#define LDSM4(r0, r1, r2, r3, addr)                                          \
    asm volatile("ldmatrix.sync.aligned.m8n8.x4.shared.b16 {%0,%1,%2,%3}, [%4];" \
                 : "=r"(r0), "=r"(r1), "=r"(r2), "=r"(r3) : "r"(addr))
#define CP16(dst, src) \
    asm volatile("cp.async.cg.shared.global [%0], [%1], 16;" :: "r"(dst), "l"(src))
#define CP_COMMIT() asm volatile("cp.async.commit_group;" ::: "memory")
#define CP_WAIT0()  asm volatile("cp.async.wait_group 0;" ::: "memory")

// ---------------------------------------------------------------------------
// Kernel 0/1: dtype detect + gather/precompute
// ---------------------------------------------------------------------------
__global__ void detect_kernel(const int* __restrict__ ngram32) {
    int all_odd_zero = 1;
    for (int i = 1; i < 64; i += 2)
        if (ngram32[i] != 0) { all_odd_zero = 0; break; }
    g_is64 = all_odd_zero;
}
__global__ void gather_kernel(const int* __restrict__ ngram32, const float* __restrict__ Wemb) {
    int f4 = blockIdx.x * blockDim.x + threadIdx.x;   // 0 .. C*N*32-1
    int d4 = f4 & 31;
    int idx = f4 >> 5;                                // c*NN + n
    int tok = g_is64 ? ngram32[2 * idx] : ngram32[idx];
    float4 v = ((const float4*)Wemb)[(size_t)tok * 32 + d4];
    g_ebh[(size_t)idx * 64 + d4 * 2 + 0] = pack_bf2(v.x, v.y);
    g_ebh[(size_t)idx * 64 + d4 * 2 + 1] = pack_bf2(v.z, v.w);
    float4 r = make_float4(tf32r(v.x), tf32r(v.y), tf32r(v.z), tf32r(v.w));
    ((float4*)g_e32)[f4] = r;
}

// ---------------------------------------------------------------------------
// smem layout (bytes)
//   bf16 tiles: 68 words/row (64 data + 4 pad); fp32 E32: 136 f/row; P: 72 f/row.
// ---------------------------------------------------------------------------
#define HSTR 68
#define ESTR 68
#define E3STR 136
#define PSTR 72
#define E3BUF (64u * E3STR * 4u)                  // 34816
#define OFF_HHI 0u
#define OFF_HLO (OFF_HHI + 128u * HSTR * 4u)      //  34816
#define OFF_EH  (OFF_HLO + 128u * HSTR * 4u)      //  69632
#define OFF_E32 (OFF_EH  + 64u * ESTR * 4u)       //  87040  (x2 buffers)
#define OFF_P   (OFF_E32 + 2u * E3BUF)            // 156672
#define OFF_RED (OFF_P   + 128u * PSTR * 4u)      // 193536
#define SMEM_TOTAL (OFF_RED + 512u)               // 194048

// ---------------------------------------------------------------------------
// Kernel 2: fused attention. grid=(L/128, C), block=256 (8 warps).
// GEMM1: 2-pass bf16 (Ah+Al)*Bh via ldmatrix, warp tile 32m x 32n.
// GEMM2: tf32 1-pass, warp tile 32l x 64d, O persistent in regs.
// E tiles streamed via cp.async (Eh single-buf in GEMM1-dead window,
// E32 double-buffered).
// ---------------------------------------------------------------------------
__global__ __launch_bounds__(256, 1)
void attn_kernel(const float* __restrict__ H,
                 const float* __restrict__ mask,
                 float* __restrict__ out) {
    extern __shared__ char sm[];
    const uint32_t smb = smem_u32(sm);
    uint32_t* Hh = (uint32_t*)(sm + OFF_HHI);
    uint32_t* Hl = (uint32_t*)(sm + OFF_HLO);
    float*    Pm = (float*)(sm + OFF_P);
    float*    Rd = (float*)(sm + OFF_RED);

    const int t = threadIdx.x, lane = t & 31, warp = t >> 5;
    const int g = lane >> 2, tig = lane & 3;
    const int lane8 = lane & 7, lm = lane >> 3;   // ldmatrix matrix id = lm
    const int wm = warp >> 1, wn = warp & 1;
    const int c = blockIdx.y, l0 = blockIdx.x * 128;

    // ---- load + split H tile [128 l][128 d] ----
    #pragma unroll
    for (int j = 0; j < 16; j++) {
        int i = t + 256 * j;
        int row = i >> 5, c4 = i & 31;
        float4 v = ((const float4*)H)[(size_t)(l0 + row) * 32 + c4];
        float hx = __bfloat162float(__float2bfloat16(v.x));
        float hy = __bfloat162float(__float2bfloat16(v.y));
        float hz = __bfloat162float(__float2bfloat16(v.z));
        float hw = __bfloat162float(__float2bfloat16(v.w));
        Hh[row * HSTR + c4 * 2 + 0] = pack_bf2(v.x, v.y);
        Hh[row * HSTR + c4 * 2 + 1] = pack_bf2(v.z, v.w);
        Hl[row * HSTR + c4 * 2 + 0] = pack_bf2(v.x - hx, v.y - hy);
        Hl[row * HSTR + c4 * 2 + 1] = pack_bf2(v.z - hz, v.w - hw);
    }
    if (t < 128) Rd[t] = 0.0f;

    float O[2][8][4];
    #pragma unroll
    for (int a = 0; a < 2; a++)
        #pragma unroll
        for (int b = 0; b < 8; b++)
            #pragma unroll
            for (int q = 0; q < 4; q++) O[a][b][q] = 0.0f;
    float rs[2][2] = {{0.f, 0.f}, {0.f, 0.f}};

    const float INV_T = 0.08838834764831845f;
    const size_t ebase = (size_t)c * NN;
    const float* mwarp = mask + ((size_t)c * L + (l0 + wm * 32)) * NN + wn * 32;

    // ldmatrix base addresses (byte): A for mc=0/1 (hi & lo), B for nc-pair 0/1
    uint32_t aH[2], aL[2], bB[2];
    #pragma unroll
    for (int mc = 0; mc < 2; mc++) {
        int row = wm * 32 + mc * 16 + (lm & 1) * 8 + lane8;
        uint32_t off = (uint32_t)(row * HSTR + (lm >> 1) * 4) * 4u;
        aH[mc] = smb + OFF_HHI + off;
        aL[mc] = smb + OFF_HLO + off;
    }
    #pragma unroll
    for (int p = 0; p < 2; p++) {
        int row = wn * 32 + (p * 2 + (lm >> 1)) * 8 + lane8;
        bB[p] = smb + OFF_EH + (uint32_t)(row * ESTR + (lm & 1) * 4) * 4u;
    }

    // ---- E-tile copy helper (cp.async), per-thread slices ----
    auto issue_copy = [&](int n0, int buf) {
        const uint32_t* srcEh = g_ebh + (ebase + n0) * 64;
        const float*    srcE3 = g_e32 + (ebase + n0) * 128;
        #pragma unroll
        for (int j = 0; j < 4; j++) {            // Eh: 1024 chunks of 16B
            int i = t + 256 * j;
            int row = i >> 4, c16 = i & 15;
            CP16(smb + OFF_EH + (uint32_t)(row * ESTR * 4 + c16 * 16),
                 srcEh + row * 64 + c16 * 4);
        }
        #pragma unroll
        for (int j = 0; j < 8; j++) {            // E32: 2048 chunks
            int i = t + 256 * j;
            int row = i >> 5, c16 = i & 31;
            CP16(smb + OFF_E32 + (uint32_t)buf * E3BUF
                     + (uint32_t)(row * E3STR * 4 + c16 * 16),
                 srcE3 + row * 128 + c16 * 4);
        }
        CP_COMMIT();
    };

    issue_copy(0, 0);   // preload tile 0

    for (int tt = 0; tt < 64; tt++) {
        const int n0 = tt * 64;
        CP_WAIT0();
        __syncthreads();   // E(tt) ready everywhere; P(tt-1) consumed

        // ---- mask prefetch into fragment layout (overlaps GEMM1) ----
        float2 mreg[2][2][4];
        {
            const float* mt = mwarp + n0;
            #pragma unroll
            for (int mc = 0; mc < 2; mc++)
                #pragma unroll
                for (int h = 0; h < 2; h++)
                    #pragma unroll
                    for (int nc = 0; nc < 4; nc++)
                        mreg[mc][h][nc] = *(const float2*)&mt[
                            (size_t)(mc * 16 + g + 8 * h) * NN + nc * 8 + 2 * tig];
        }

        // ---- GEMM1: S = (Ah + Al) * Bh, 2-pass bf16, ldmatrix frags ----
        float S[2][4][4];
        #pragma unroll
        for (int a = 0; a < 2; a++)
            #pragma unroll
            for (int b = 0; b < 4; b++)
                #pragma unroll
                for (int q = 0; q < 4; q++) S[a][b][q] = 0.0f;

        #pragma unroll
        for (int kk = 0; kk < 8; kk++) {
            const uint32_t kb = (uint32_t)kk * 32u;
            uint32_t ah[2][4], al[2][4], bh[4][2];
            LDSM4(ah[0][0], ah[0][1], ah[0][2], ah[0][3], aH[0] + kb);
            LDSM4(ah[1][0], ah[1][1], ah[1][2], ah[1][3], aH[1] + kb);
            LDSM4(al[0][0], al[0][1], al[0][2], al[0][3], aL[0] + kb);
            LDSM4(al[1][0], al[1][1], al[1][2], al[1][3], aL[1] + kb);
            LDSM4(bh[0][0], bh[0][1], bh[1][0], bh[1][1], bB[0] + kb);
            LDSM4(bh[2][0], bh[2][1], bh[3][0], bh[3][1], bB[1] + kb);
            #pragma unroll
            for (int mc = 0; mc < 2; mc++)
                #pragma unroll
                for (int nc = 0; nc < 4; nc++) {
                    mma_bf16(S[mc][nc], ah[mc], bh[nc][0], bh[nc][1]);
                    mma_bf16(S[mc][nc], al[mc], bh[nc][0], bh[nc][1]);
                }
        }

        // ---- epilogue: P = exp(S/temper)*clip(mask) -> smem (tf32) ----
        #pragma unroll
        for (int mc = 0; mc < 2; mc++)
            #pragma unroll
            for (int h = 0; h < 2; h++) {
                int row = wm * 32 + mc * 16 + g + 8 * h;
                #pragma unroll
                for (int nc = 0; nc < 4; nc++) {
                    float2 m = mreg[mc][h][nc];
                    float m0 = fminf(fmaxf(m.x, 0.0f), 1.0f);
                    float m1 = fminf(fmaxf(m.y, 0.0f), 1.0f);
                    float p0 = __expf(S[mc][nc][2 * h + 0] * INV_T) * m0;
                    float p1 = __expf(S[mc][nc][2 * h + 1] * INV_T) * m1;
                    rs[mc][h] += p0 + p1;
                    *(float2*)&Pm[row * PSTR + wn * 32 + nc * 8 + 2 * tig] =
                        make_float2(tf32r(p0), tf32r(p1));
                }
            }
        __syncthreads();   // P visible; Eh(tt) + E32 buf (tt+1)&1 now dead

        // ---- prefetch E(tt+1) while GEMM2 runs ----
        if (tt < 63) issue_copy(n0 + 64, (tt + 1) & 1);

        // ---- GEMM2: O += P(tf32) x E32[buf tt&1], warp tile 32l x 64d ----
        uint32_t* Pw = (uint32_t*)Pm;
        uint32_t* Ew = (uint32_t*)(sm + OFF_E32 + (uint32_t)(tt & 1) * E3BUF);
        #pragma unroll
        for (int kc = 0; kc < 8; kc++) {
            uint32_t pa[2][4];
            #pragma unroll
            for (int mc = 0; mc < 2; mc++) {
                int r = (wm * 32 + mc * 16 + g) * PSTR + kc * 8 + tig;
                pa[mc][0] = Pw[r];              pa[mc][2] = Pw[r + 4];
                pa[mc][1] = Pw[r + 8 * PSTR];   pa[mc][3] = Pw[r + 8 * PSTR + 4];
            }
            #pragma unroll
            for (int nc = 0; nc < 8; nc++) {
                int bw = (kc * 8 + tig) * E3STR + wn * 64 + nc * 8 + g;
                uint32_t b0 = Ew[bw], b1 = Ew[bw + 4 * E3STR];
                mma_tf32(O[0][nc], pa[0], b0, b1);
                mma_tf32(O[1][nc], pa[1], b0, b1);
            }
        }
    }

    // ---- rowsum reduce: quad shfl + smem atomic ----
    #pragma unroll
    for (int mc = 0; mc < 2; mc++)
        #pragma unroll
        for (int h = 0; h < 2; h++) {
            float v = rs[mc][h];
            v += __shfl_xor_sync(0xFFFFFFFFu, v, 1);
            v += __shfl_xor_sync(0xFFFFFFFFu, v, 2);
            if (tig == 0) atomicAdd(&Rd[wm * 32 + mc * 16 + g + 8 * h], v);
        }
    __syncthreads();

    // ---- normalize + writeout ----
    #pragma unroll
    for (int mc = 0; mc < 2; mc++)
        #pragma unroll
        for (int h = 0; h < 2; h++) {
            int row = wm * 32 + mc * 16 + g + 8 * h;
            float inv = 1.0f / (Rd[row] + 1e-10f);
            float* orow = out + (size_t)(l0 + row) * (C * D) + c * D + wn * 64;
            #pragma unroll
            for (int nc = 0; nc < 8; nc++)
                *(float2*)&orow[nc * 8 + 2 * tig] =
                    make_float2(O[mc][nc][2 * h + 0] * inv,
                                O[mc][nc][2 * h + 1] * inv);
        }
}

// ---------------------------------------------------------------------------
extern "C" void kernel_launch(void* const* d_in, const int* in_sizes, int n_in,
                              void* d_out, int out_size) {
    const int*   ngram32 = (const int*)d_in[0];
    const float* H       = (const float*)d_in[1];
    const float* mask    = (const float*)d_in[2];
    const float* Wemb    = (const float*)d_in[4];
    float*       out     = (float*)d_out;

    cudaFuncSetAttribute(attn_kernel, cudaFuncAttributeMaxDynamicSharedMemorySize, SMEM_TOTAL);

    detect_kernel<<<1, 1>>>(ngram32);
    gather_kernel<<<C * NN * (D / 4) / 256, 256>>>(ngram32, Wemb);
    dim3 grid(L / 128, C);
    attn_kernel<<<grid, 256, SMEM_TOTAL>>>(H, mask, out);
}

// round 11
// speedup vs baseline: 9.4961x; 1.7562x over previous
#include <cuda_runtime.h>
#include <cuda_fp16.h>
#include <cstdint>

#define C 8
#define L 4096
#define NN 4096
#define D 128
#define V 100000

// ---------------------------------------------------------------------------
// precomputed fp16 embeddings + dtype flag
// ---------------------------------------------------------------------------
__device__ uint32_t g_e16[(size_t)C * NN * 64];   // fp16(E) packed pairs, 8 MB
__device__ int      g_is64;

// ---------------------------------------------------------------------------
// helpers
// ---------------------------------------------------------------------------
__device__ __forceinline__ uint32_t smem_u32(const void* p) {
    uint32_t a;
    asm("{ .reg .u64 t; cvta.to.shared.u64 t, %1; cvt.u32.u64 %0, t; }" : "=r"(a) : "l"(p));
    return a;
}
__device__ __forceinline__ uint32_t pack_h2(float x, float y) {
    __half2 h = __floats2half2_rn(x, y);     // .x = x (low 16 bits)
    return *(uint32_t*)&h;
}
__device__ __forceinline__ void mma_fp16(float c[4], const uint32_t a[4],
                                         uint32_t b0, uint32_t b1) {
    asm volatile("mma.sync.aligned.m16n8k16.row.col.f32.f16.f16.f32 "
                 "{%0,%1,%2,%3}, {%4,%5,%6,%7}, {%8,%9}, {%0,%1,%2,%3};"
                 : "+f"(c[0]), "+f"(c[1]), "+f"(c[2]), "+f"(c[3])
                 : "r"(a[0]), "r"(a[1]), "r"(a[2]), "r"(a[3]), "r"(b0), "r"(b1));
}
#define LDSM4(r0, r1, r2, r3, addr)                                              \
    asm volatile("ldmatrix.sync.aligned.m8n8.x4.shared.b16 {%0,%1,%2,%3}, [%4];" \
                 : "=r"(r0), "=r"(r1), "=r"(r2), "=r"(r3) : "r"(addr))
#define LDSM4T(r0, r1, r2, r3, addr)                                             \
    asm volatile("ldmatrix.sync.aligned.m8n8.x4.trans.shared.b16 {%0,%1,%2,%3}, [%4];" \
                 : "=r"(r0), "=r"(r1), "=r"(r2), "=r"(r3) : "r"(addr))
#define CP16(dst, src) \
    asm volatile("cp.async.cg.shared.global [%0], [%1], 16;" :: "r"(dst), "l"(src))
#define CP_COMMIT() asm volatile("cp.async.commit_group;" ::: "memory")
#define CP_WAIT0()  asm volatile("cp.async.wait_group 0;" ::: "memory")

// ---------------------------------------------------------------------------
// Kernel 0/1: dtype detect + gather (fp16 precompute)
// ---------------------------------------------------------------------------
__global__ void detect_kernel(const int* __restrict__ ngram32) {
    int all_odd_zero = 1;
    for (int i = 1; i < 64; i += 2)
        if (ngram32[i] != 0) { all_odd_zero = 0; break; }
    g_is64 = all_odd_zero;
}
__global__ void gather_kernel(const int* __restrict__ ngram32, const float* __restrict__ Wemb) {
    int f4 = blockIdx.x * blockDim.x + threadIdx.x;   // 0 .. C*N*32-1
    int d4 = f4 & 31;
    int idx = f4 >> 5;                                // c*NN + n
    int tok = g_is64 ? ngram32[2 * idx] : ngram32[idx];
    float4 v = ((const float4*)Wemb)[(size_t)tok * 32 + d4];
    g_e16[(size_t)idx * 64 + d4 * 2 + 0] = pack_h2(v.x, v.y);
    g_e16[(size_t)idx * 64 + d4 * 2 + 1] = pack_h2(v.z, v.w);
}

// ---------------------------------------------------------------------------
// smem layout (bytes). fp16 tiles, padded word strides:
//   H: [128][68 words] (128 fp16 + 8 pad)   -> ldmatrix banks 4g+tig distinct
//   E: [64][68 words]  x2 buffers           -> serves GEMM1 (ldsm) + GEMM2 (ldsm.trans)
//   P: [128][36 words] (64 fp16 + 8 pad)
// ---------------------------------------------------------------------------
#define HSTR 68
#define ESTR 68
#define PSTR 36
#define EBUF  17408u
#define OFF_H 0u
#define OFF_E 34816u
#define OFF_P 69632u
#define OFF_RED 88064u
#define SMEM_TOTAL 88576u

// ---------------------------------------------------------------------------
// Kernel 2: fused attention. grid=(L/128, C), block=256 (8 warps), 2 CTAs/SM.
// GEMM1: 1-pass fp16, warp tile 32m x 32n. GEMM2: 1-pass fp16, warp 32l x 64d.
// Single fp16 E tile dual-used by both GEMMs; P round-trips as fp16.
// ---------------------------------------------------------------------------
__global__ __launch_bounds__(256, 2)
void attn_kernel(const float* __restrict__ H,
                 const float* __restrict__ mask,
                 float* __restrict__ out) {
    extern __shared__ char sm[];
    const uint32_t smb = smem_u32(sm);
    uint32_t* Hs = (uint32_t*)(sm + OFF_H);
    float*    Rd = (float*)(sm + OFF_RED);

    const int t = threadIdx.x, lane = t & 31, warp = t >> 5;
    const int g = lane >> 2, tig = lane & 3;
    const int lane8 = lane & 7, lm = lane >> 3;
    const int wm = warp >> 1, wn = warp & 1;
    const int c = blockIdx.y, l0 = blockIdx.x * 128;

    // ---- load H tile [128 l][128 d] as fp16 ----
    #pragma unroll
    for (int j = 0; j < 16; j++) {
        int i = t + 256 * j;
        int row = i >> 5, c4 = i & 31;
        float4 v = ((const float4*)H)[(size_t)(l0 + row) * 32 + c4];
        Hs[row * HSTR + c4 * 2 + 0] = pack_h2(v.x, v.y);
        Hs[row * HSTR + c4 * 2 + 1] = pack_h2(v.z, v.w);
    }
    if (t < 128) Rd[t] = 0.0f;

    float O[2][8][4];
    #pragma unroll
    for (int a = 0; a < 2; a++)
        #pragma unroll
        for (int b = 0; b < 8; b++)
            #pragma unroll
            for (int q = 0; q < 4; q++) O[a][b][q] = 0.0f;
    float rs[2][2] = {{0.f, 0.f}, {0.f, 0.f}};

    const float INV_T = 0.08838834764831845f;
    const size_t ebase = (size_t)c * NN;
    const float* mwarp = mask + ((size_t)c * L + (l0 + wm * 32)) * NN + wn * 32;

    // ldmatrix lane-base offsets (bytes, relative to tile base)
    uint32_t aH[2], pP[2];     // A frags: H (GEMM1), P (GEMM2)
    #pragma unroll
    for (int mc = 0; mc < 2; mc++) {
        int row = wm * 32 + mc * 16 + (lm & 1) * 8 + lane8;
        aH[mc] = smb + OFF_H + (uint32_t)(row * HSTR + (lm >> 1) * 4) * 4u;
        pP[mc] = smb + OFF_P + (uint32_t)(row * PSTR + (lm >> 1) * 4) * 4u;
    }
    uint32_t bBr[2];           // GEMM1 B (E rows [n][k]), relative to E buffer
    #pragma unroll
    for (int p = 0; p < 2; p++) {
        int row = wn * 32 + (p * 2 + (lm >> 1)) * 8 + lane8;
        bBr[p] = (uint32_t)(row * ESTR + (lm & 1) * 4) * 4u;
    }
    // GEMM2 B via ldmatrix.trans: E[k=n rows][d cols]; lane base (kc=0, nc2=0)
    const uint32_t bTr = (uint32_t)(((lm & 1) * 8 + lane8) * (ESTR * 4))
                       + (uint32_t)(wn * 128 + (lm >> 1) * 16);

    // ---- E-tile copy (cp.async): 64 rows x 256B ----
    auto issue_copy = [&](int n0, int buf) {
        const uint32_t* srcE = g_e16 + (ebase + n0) * 64;
        uint32_t dst = smb + OFF_E + (uint32_t)buf * EBUF;
        #pragma unroll
        for (int j = 0; j < 4; j++) {
            int i = t + 256 * j;
            int row = i >> 4, c16 = i & 15;
            CP16(dst + (uint32_t)(row * ESTR + c16 * 4) * 4u,
                 srcE + row * 64 + c16 * 4);
        }
        CP_COMMIT();
    };

    issue_copy(0, 0);

    for (int tt = 0; tt < 64; tt++) {
        const int n0 = tt * 64;
        const uint32_t ebuf = smb + OFF_E + (uint32_t)(tt & 1) * EBUF;
        CP_WAIT0();
        __syncthreads();   // E(tt) ready; P(tt-1) consumed by GEMM2

        // ---- GEMM1: S = H x E^T, 1-pass fp16 ----
        float S[2][4][4];
        #pragma unroll
        for (int a = 0; a < 2; a++)
            #pragma unroll
            for (int b = 0; b < 4; b++)
                #pragma unroll
                for (int q = 0; q < 4; q++) S[a][b][q] = 0.0f;

        #pragma unroll
        for (int kk = 0; kk < 8; kk++) {
            const uint32_t kb = (uint32_t)kk * 32u;
            uint32_t ah[2][4], bh[4][2];
            LDSM4(ah[0][0], ah[0][1], ah[0][2], ah[0][3], aH[0] + kb);
            LDSM4(ah[1][0], ah[1][1], ah[1][2], ah[1][3], aH[1] + kb);
            LDSM4(bh[0][0], bh[0][1], bh[1][0], bh[1][1], ebuf + bBr[0] + kb);
            LDSM4(bh[2][0], bh[2][1], bh[3][0], bh[3][1], ebuf + bBr[1] + kb);
            #pragma unroll
            for (int mc = 0; mc < 2; mc++)
                #pragma unroll
                for (int nc = 0; nc < 4; nc++)
                    mma_fp16(S[mc][nc], ah[mc], bh[nc][0], bh[nc][1]);
        }

        // ---- epilogue: P = exp(S/temper)*clip(mask) -> smem fp16 ----
        #pragma unroll
        for (int mc = 0; mc < 2; mc++)
            #pragma unroll
            for (int h = 0; h < 2; h++) {
                int row = wm * 32 + mc * 16 + g + 8 * h;
                const float* mrow = mwarp + (size_t)(mc * 16 + g + 8 * h) * NN + n0;
                float2 m[4];
                #pragma unroll
                for (int nc = 0; nc < 4; nc++)
                    m[nc] = *(const float2*)&mrow[nc * 8 + 2 * tig];
                #pragma unroll
                for (int nc = 0; nc < 4; nc++) {
                    float m0 = fminf(fmaxf(m[nc].x, 0.0f), 1.0f);
                    float m1 = fminf(fmaxf(m[nc].y, 0.0f), 1.0f);
                    float p0 = __expf(S[mc][nc][2 * h + 0] * INV_T) * m0;
                    float p1 = __expf(S[mc][nc][2 * h + 1] * INV_T) * m1;
                    rs[mc][h] += p0 + p1;
                    *(__half2*)(sm + OFF_P + row * (PSTR * 4)
                                + (wn * 32 + nc * 8 + 2 * tig) * 2) =
                        __floats2half2_rn(p0, p1);
                }
            }
        __syncthreads();   // P visible; E buf (tt+1)&1 free

        // ---- prefetch E(tt+1) while GEMM2 runs ----
        if (tt < 63) issue_copy(n0 + 64, (tt + 1) & 1);

        // ---- GEMM2: O += P x E, 1-pass fp16 (B via ldmatrix.trans) ----
        #pragma unroll
        for (int kc = 0; kc < 4; kc++) {
            const uint32_t kb = (uint32_t)kc * 32u;
            uint32_t pa[2][4];
            LDSM4(pa[0][0], pa[0][1], pa[0][2], pa[0][3], pP[0] + kb);
            LDSM4(pa[1][0], pa[1][1], pa[1][2], pa[1][3], pP[1] + kb);
            #pragma unroll
            for (int nc2 = 0; nc2 < 4; nc2++) {
                uint32_t b0, b1, b2, b3;
                LDSM4T(b0, b1, b2, b3,
                       ebuf + bTr + (uint32_t)kc * (16u * ESTR * 4u) + (uint32_t)nc2 * 32u);
                mma_fp16(O[0][2 * nc2 + 0], pa[0], b0, b1);
                mma_fp16(O[1][2 * nc2 + 0], pa[1], b0, b1);
                mma_fp16(O[0][2 * nc2 + 1], pa[0], b2, b3);
                mma_fp16(O[1][2 * nc2 + 1], pa[1], b2, b3);
            }
        }
    }

    // ---- rowsum reduce: quad shfl + smem atomic ----
    #pragma unroll
    for (int mc = 0; mc < 2; mc++)
        #pragma unroll
        for (int h = 0; h < 2; h++) {
            float v = rs[mc][h];
            v += __shfl_xor_sync(0xFFFFFFFFu, v, 1);
            v += __shfl_xor_sync(0xFFFFFFFFu, v, 2);
            if (tig == 0) atomicAdd(&Rd[wm * 32 + mc * 16 + g + 8 * h], v);
        }
    __syncthreads();

    // ---- normalize + writeout ----
    #pragma unroll
    for (int mc = 0; mc < 2; mc++)
        #pragma unroll
        for (int h = 0; h < 2; h++) {
            int row = wm * 32 + mc * 16 + g + 8 * h;
            float inv = 1.0f / (Rd[row] + 1e-10f);
            float* orow = out + (size_t)(l0 + row) * (C * D) + c * D + wn * 64;
            #pragma unroll
            for (int nc = 0; nc < 8; nc++)
                *(float2*)&orow[nc * 8 + 2 * tig] =
                    make_float2(O[mc][nc][2 * h + 0] * inv,
                                O[mc][nc][2 * h + 1] * inv);
        }
}

// ---------------------------------------------------------------------------
extern "C" void kernel_launch(void* const* d_in, const int* in_sizes, int n_in,
                              void* d_out, int out_size) {
    const int*   ngram32 = (const int*)d_in[0];
    const float* H       = (const float*)d_in[1];
    const float* mask    = (const float*)d_in[2];
    const float* Wemb    = (const float*)d_in[4];
    float*       out     = (float*)d_out;

    cudaFuncSetAttribute(attn_kernel, cudaFuncAttributeMaxDynamicSharedMemorySize, SMEM_TOTAL);

    detect_kernel<<<1, 1>>>(ngram32);
    gather_kernel<<<C * NN * (D / 4) / 256, 256>>>(ngram32, Wemb);
    dim3 grid(L / 128, C);
    attn_kernel<<<grid, 256, SMEM_TOTAL>>>(H, mask, out);
}

// round 12
// speedup vs baseline: 9.9163x; 1.0443x over previous
#include <cuda_runtime.h>
#include <cuda_fp16.h>
#include <cstdint>

#define C 8
#define L 4096
#define NN 4096
#define D 128
#define V 100000

// ---------------------------------------------------------------------------
// precomputed fp16 embeddings
// ---------------------------------------------------------------------------
__device__ uint32_t g_e16[(size_t)C * NN * 64];   // fp16(E) packed pairs, 8 MB

// ---------------------------------------------------------------------------
// helpers
// ---------------------------------------------------------------------------
__device__ __forceinline__ uint32_t smem_u32(const void* p) {
    uint32_t a;
    asm("{ .reg .u64 t; cvta.to.shared.u64 t, %1; cvt.u32.u64 %0, t; }" : "=r"(a) : "l"(p));
    return a;
}
__device__ __forceinline__ uint32_t pack_h2(float x, float y) {
    __half2 h = __floats2half2_rn(x, y);     // .x = x (low 16 bits)
    return *(uint32_t*)&h;
}
__device__ __forceinline__ void mma_fp16(float c[4], const uint32_t a[4],
                                         uint32_t b0, uint32_t b1) {
    asm volatile("mma.sync.aligned.m16n8k16.row.col.f32.f16.f16.f32 "
                 "{%0,%1,%2,%3}, {%4,%5,%6,%7}, {%8,%9}, {%0,%1,%2,%3};"
                 : "+f"(c[0]), "+f"(c[1]), "+f"(c[2]), "+f"(c[3])
                 : "r"(a[0]), "r"(a[1]), "r"(a[2]), "r"(a[3]), "r"(b0), "r"(b1));
}
#define LDSM4(r0, r1, r2, r3, addr)                                              \
    asm volatile("ldmatrix.sync.aligned.m8n8.x4.shared.b16 {%0,%1,%2,%3}, [%4];" \
                 : "=r"(r0), "=r"(r1), "=r"(r2), "=r"(r3) : "r"(addr))
#define LDSM4T(r0, r1, r2, r3, addr)                                             \
    asm volatile("ldmatrix.sync.aligned.m8n8.x4.trans.shared.b16 {%0,%1,%2,%3}, [%4];" \
                 : "=r"(r0), "=r"(r1), "=r"(r2), "=r"(r3) : "r"(addr))
#define CP16(dst, src) \
    asm volatile("cp.async.cg.shared.global [%0], [%1], 16;" :: "r"(dst), "l"(src))
#define CP_COMMIT() asm volatile("cp.async.commit_group;" ::: "memory")
#define CP_WAIT0()  asm volatile("cp.async.wait_group 0;" ::: "memory")

// ---------------------------------------------------------------------------
// Kernel 1: gather + fp16 precompute (dtype self-detect via odd-word probe:
// int64 little-endian => odd int32 words are zero high-halves; for genuine
// int32 tokens P(4 specific tokens all zero) ~ 1e-20)
// ---------------------------------------------------------------------------
__global__ void gather_kernel(const int* __restrict__ ngram32, const float* __restrict__ Wemb) {
    int f4 = blockIdx.x * blockDim.x + threadIdx.x;   // 0 .. C*N*32-1
    int d4 = f4 & 31;
    int idx = f4 >> 5;                                // c*NN + n
    int probe = ngram32[1] | ngram32[3] | ngram32[5] | ngram32[7];
    int tok = (probe == 0) ? ngram32[2 * idx] : ngram32[idx];
    float4 v = ((const float4*)Wemb)[(size_t)tok * 32 + d4];
    g_e16[(size_t)idx * 64 + d4 * 2 + 0] = pack_h2(v.x, v.y);
    g_e16[(size_t)idx * 64 + d4 * 2 + 1] = pack_h2(v.z, v.w);
}

// ---------------------------------------------------------------------------
// smem layout (bytes). fp16 tiles, 68-word rows (128 fp16 + 8 pad).
//   H: [128][68]    E: [64][68] x2 buffers    Rd: 128 floats
// ---------------------------------------------------------------------------
#define HSTR 68
#define ESTR 68
#define EBUF  17408u
#define OFF_H 0u
#define OFF_E 34816u
#define OFF_RED 69632u
#define SMEM_TOTAL 70144u

// ---------------------------------------------------------------------------
// Kernel 2: fused attention. grid=(L/128, C), block=256 (8 warps), 2 CTAs/SM.
// Warp owns 16 l-rows. GEMM1: 16m x 64n fp16. Epilogue in registers.
// GEMM2: 16l x 128d fp16 with A-fragments packed directly from S accumulators
// (C-frag == A-frag layout when k-dim = GEMM1 n-dim). One sync per tile.
// ---------------------------------------------------------------------------
__global__ __launch_bounds__(256, 2)
void attn_kernel(const float* __restrict__ H,
                 const float* __restrict__ mask,
                 float* __restrict__ out) {
    extern __shared__ char sm[];
    const uint32_t smb = smem_u32(sm);
    uint32_t* Hs = (uint32_t*)(sm + OFF_H);
    float*    Rd = (float*)(sm + OFF_RED);

    const int t = threadIdx.x, lane = t & 31, wm = t >> 5;
    const int g = lane >> 2, tig = lane & 3;
    const int lane8 = lane & 7, lm = lane >> 3;
    const int c = blockIdx.y, l0 = blockIdx.x * 128;

    // ---- load H tile [128 l][128 d] as fp16 ----
    #pragma unroll
    for (int j = 0; j < 16; j++) {
        int i = t + 256 * j;
        int row = i >> 5, c4 = i & 31;
        float4 v = ((const float4*)H)[(size_t)(l0 + row) * 32 + c4];
        Hs[row * HSTR + c4 * 2 + 0] = pack_h2(v.x, v.y);
        Hs[row * HSTR + c4 * 2 + 1] = pack_h2(v.z, v.w);
    }
    if (t < 128) Rd[t] = 0.0f;

    float O[16][4];
    #pragma unroll
    for (int a = 0; a < 16; a++)
        #pragma unroll
        for (int q = 0; q < 4; q++) O[a][q] = 0.0f;
    float rs[2] = {0.f, 0.f};

    const float INV_T = 0.08838834764831845f;
    const size_t ebase = (size_t)c * NN;
    const float* mbase0 = mask + ((size_t)c * L + (l0 + 16 * wm)) * NN;

    // ldmatrix lane-base addresses
    const uint32_t aH = smb + OFF_H +
        (uint32_t)((16 * wm + (lm & 1) * 8 + lane8) * HSTR + (lm >> 1) * 4) * 4u;
    uint32_t bB[4];                       // GEMM1 B: E rows [n][k], rel to ebuf
    #pragma unroll
    for (int p = 0; p < 4; p++) {
        int row = (2 * p + (lm >> 1)) * 8 + lane8;
        bB[p] = (uint32_t)(row * ESTR + (lm & 1) * 4) * 4u;
    }
    // GEMM2 B via ldmatrix.trans on E[n][d], rel to ebuf
    const uint32_t bTr = (uint32_t)(((lm & 1) * 8 + lane8) * (ESTR * 4))
                       + (uint32_t)((lm >> 1) * 16);

    // ---- E-tile copy (cp.async): 64 rows x 256B, 4 chunks/thread ----
    auto issue_copy = [&](int n0, int buf) {
        const uint32_t* srcE = g_e16 + (ebase + n0) * 64;
        uint32_t dst = smb + OFF_E + (uint32_t)buf * EBUF;
        #pragma unroll
        for (int j = 0; j < 4; j++) {
            int i = t + 256 * j;
            int row = i >> 4, c16 = i & 15;
            CP16(dst + (uint32_t)(row * ESTR + c16 * 4) * 4u,
                 srcE + row * 64 + c16 * 4);
        }
        CP_COMMIT();
    };

    issue_copy(0, 0);

    for (int tt = 0; tt < 64; tt++) {
        const int n0 = tt * 64;
        const uint32_t ebuf = smb + OFF_E + (uint32_t)(tt & 1) * EBUF;
        CP_WAIT0();
        __syncthreads();   // E(tt) visible everywhere; all warps done with tt-1

        // prefetch E(tt+1) into the buffer freed at the sync
        if (tt < 63) issue_copy(n0 + 64, (tt + 1) & 1);

        // ---- GEMM1: S[16m x 64n] = H x E^T ----
        float S[8][4];
        #pragma unroll
        for (int a = 0; a < 8; a++)
            #pragma unroll
            for (int q = 0; q < 4; q++) S[a][q] = 0.0f;

        #pragma unroll
        for (int kk = 0; kk < 8; kk++) {
            const uint32_t kb = (uint32_t)kk * 32u;
            uint32_t ah[4];
            LDSM4(ah[0], ah[1], ah[2], ah[3], aH + kb);
            #pragma unroll
            for (int p = 0; p < 4; p++) {
                uint32_t r0, r1, r2, r3;
                LDSM4(r0, r1, r2, r3, ebuf + bB[p] + kb);
                mma_fp16(S[2 * p + 0], ah, r0, r1);
                mma_fp16(S[2 * p + 1], ah, r2, r3);
            }
        }

        // ---- epilogue (registers only): P = exp(S/temper)*clip(mask) ----
        #pragma unroll
        for (int h = 0; h < 2; h++) {
            const float* mr = mbase0 + (size_t)(g + 8 * h) * NN + n0;
            float2 m[8];
            #pragma unroll
            for (int nc = 0; nc < 8; nc++)
                m[nc] = *(const float2*)&mr[8 * nc + 2 * tig];
            #pragma unroll
            for (int nc = 0; nc < 8; nc++) {
                float m0 = fminf(fmaxf(m[nc].x, 0.0f), 1.0f);
                float m1 = fminf(fmaxf(m[nc].y, 0.0f), 1.0f);
                float p0 = __expf(S[nc][2 * h + 0] * INV_T) * m0;
                float p1 = __expf(S[nc][2 * h + 1] * INV_T) * m1;
                rs[h] += p0 + p1;
                S[nc][2 * h + 0] = p0;
                S[nc][2 * h + 1] = p1;
            }
        }

        // ---- GEMM2: O[16l x 128d] += P x E ; A packed from S accumulators ----
        #pragma unroll
        for (int kc = 0; kc < 4; kc++) {
            uint32_t pa[4];
            pa[0] = pack_h2(S[2 * kc + 0][0], S[2 * kc + 0][1]);   // (g,   k0..1)
            pa[1] = pack_h2(S[2 * kc + 0][2], S[2 * kc + 0][3]);   // (g+8, k0..1)
            pa[2] = pack_h2(S[2 * kc + 1][0], S[2 * kc + 1][1]);   // (g,   k8..9)
            pa[3] = pack_h2(S[2 * kc + 1][2], S[2 * kc + 1][3]);   // (g+8, k8..9)
            const uint32_t kbase = ebuf + bTr + (uint32_t)kc * (16u * ESTR * 4u);
            #pragma unroll
            for (int j = 0; j < 8; j++) {
                uint32_t b0, b1, b2, b3;
                LDSM4T(b0, b1, b2, b3, kbase + (uint32_t)j * 32u);
                mma_fp16(O[2 * j + 0], pa, b0, b1);
                mma_fp16(O[2 * j + 1], pa, b2, b3);
            }
        }
    }

    // ---- rowsum: quad reduce, exclusive row ownership -> plain store ----
    #pragma unroll
    for (int h = 0; h < 2; h++) {
        float v = rs[h];
        v += __shfl_xor_sync(0xFFFFFFFFu, v, 1);
        v += __shfl_xor_sync(0xFFFFFFFFu, v, 2);
        if (tig == 0) Rd[16 * wm + g + 8 * h] = v;
    }
    __syncthreads();

    // ---- normalize + writeout ----
    #pragma unroll
    for (int h = 0; h < 2; h++) {
        int row = 16 * wm + g + 8 * h;
        float inv = 1.0f / (Rd[row] + 1e-10f);
        float* orow = out + (size_t)(l0 + row) * (C * D) + c * D;
        #pragma unroll
        for (int j = 0; j < 16; j++)
            *(float2*)&orow[8 * j + 2 * tig] =
                make_float2(O[j][2 * h + 0] * inv, O[j][2 * h + 1] * inv);
    }
}

// ---------------------------------------------------------------------------
extern "C" void kernel_launch(void* const* d_in, const int* in_sizes, int n_in,
                              void* d_out, int out_size) {
    const int*   ngram32 = (const int*)d_in[0];
    const float* H       = (const float*)d_in[1];
    const float* mask    = (const float*)d_in[2];
    const float* Wemb    = (const float*)d_in[4];
    float*       out     = (float*)d_out;

    cudaFuncSetAttribute(attn_kernel, cudaFuncAttributeMaxDynamicSharedMemorySize, SMEM_TOTAL);

    gather_kernel<<<C * NN * (D / 4) / 256, 256>>>(ngram32, Wemb);
    dim3 grid(L / 128, C);
    attn_kernel<<<grid, 256, SMEM_TOTAL>>>(H, mask, out);
}